// round 3
// baseline (speedup 1.0000x reference)
#include <cuda_runtime.h>

// out[n, d, t] = mean over d' of in[n, d', t]
// in: [32768, 64, 64] fp32. Pure streaming: 512MB read + 512MB write.
// At the B300 LTS cap (~6300 B/cyc, path-independent) this is roofline-bound;
// this version removes wave quantization: 1024 blocks = single resident wave
// (7 blocks/SM), each thread runs exactly 2 perfectly-balanced iterations.

static constexpr int N_AGENTS = 32768;
static constexpr int FEAT_DIM = 64;
static constexpr int QUADS_PER_ROW = 16;   // 64 t / 4
static constexpr int F4_PER_AGENT = 1024;  // 64*64/4
static constexpr int TOTAL_ITEMS = N_AGENTS * QUADS_PER_ROW;  // 524288

__global__ void __launch_bounds__(256)
mean_bcast_kernel(const float4* __restrict__ in, float4* __restrict__ out) {
    const int stride = gridDim.x * blockDim.x;           // 262144
    const float inv = 1.0f / (float)FEAT_DIM;

    for (int gid = blockIdx.x * blockDim.x + threadIdx.x;
         gid < TOTAL_ITEMS; gid += stride) {
        int agent = gid >> 4;
        int tq = gid & 15;

        const float4* __restrict__ row = in + (size_t)agent * F4_PER_AGENT + tq;
        float4* __restrict__ orow = out + (size_t)agent * F4_PER_AGENT + tq;

        float ax = 0.f, ay = 0.f, az = 0.f, aw = 0.f;
        #pragma unroll 16
        for (int d = 0; d < FEAT_DIM; d++) {
            float4 v = __ldcs(&row[d * QUADS_PER_ROW]);
            ax += v.x; ay += v.y; az += v.z; aw += v.w;
        }
        float4 m;
        m.x = ax * inv; m.y = ay * inv; m.z = az * inv; m.w = aw * inv;

        #pragma unroll 16
        for (int d = 0; d < FEAT_DIM; d++) {
            __stcs(&orow[d * QUADS_PER_ROW], m);
        }
    }
}

extern "C" void kernel_launch(void* const* d_in, const int* in_sizes, int n_in,
                              void* d_out, int out_size) {
    const float4* in = (const float4*)d_in[0];
    float4* out = (float4*)d_out;
    // seq_start_end (d_in[1]) is a no-op: contiguous partition, mean is per-agent.
    // 1024 blocks x 256 threads = 262144 threads; each does exactly 2 items.
    mean_bcast_kernel<<<1024, 256>>>(in, out);
}

// round 4
// speedup vs baseline: 1.0185x; 1.0185x over previous
#include <cuda_runtime.h>

// out[n, d, t] = mean over d' of in[n, d', t]
// in: [32768, 64, 64] fp32. Pure streaming: 512MB read + 512MB write.
// Roofline-bound at the B300 DRAM/LTS mixed-stream ceiling (~6.3TB/s measured).
// R3 lesson: full thread-count occupancy is mandatory (persistent grid lost 4%).
// This round: same 16-threads/agent coalesced layout, but 128-thread blocks
// (4096 blocks, 16/SM) for finer work-steal granularity on the 0.73 tail wave.

static constexpr int N_AGENTS = 32768;
static constexpr int FEAT_DIM = 64;
static constexpr int QUADS_PER_ROW = 16;   // 64 t / 4
static constexpr int F4_PER_AGENT = 1024;  // 64*64/4

__global__ void __launch_bounds__(128)
mean_bcast_kernel(const float4* __restrict__ in, float4* __restrict__ out) {
    int gid = blockIdx.x * blockDim.x + threadIdx.x;   // 0 .. 32768*16-1
    int agent = gid >> 4;
    int tq = gid & 15;

    const float4* __restrict__ row = in + (size_t)agent * F4_PER_AGENT + tq;
    float4* __restrict__ orow = out + (size_t)agent * F4_PER_AGENT + tq;

    float ax = 0.f, ay = 0.f, az = 0.f, aw = 0.f;
    #pragma unroll 8
    for (int d = 0; d < FEAT_DIM; d++) {
        float4 v = __ldcs(&row[d * QUADS_PER_ROW]);
        ax += v.x; ay += v.y; az += v.z; aw += v.w;
    }
    const float inv = 1.0f / (float)FEAT_DIM;
    float4 m;
    m.x = ax * inv; m.y = ay * inv; m.z = az * inv; m.w = aw * inv;

    #pragma unroll 8
    for (int d = 0; d < FEAT_DIM; d++) {
        __stcs(&orow[d * QUADS_PER_ROW], m);
    }
}

extern "C" void kernel_launch(void* const* d_in, const int* in_sizes, int n_in,
                              void* d_out, int out_size) {
    const float4* in = (const float4*)d_in[0];
    float4* out = (float4*)d_out;
    // seq_start_end (d_in[1]) is a no-op: contiguous partition, mean is per-agent.
    int total_threads = N_AGENTS * QUADS_PER_ROW;   // 524288
    int block = 128;
    int grid = total_threads / block;               // 4096
    mean_bcast_kernel<<<grid, block>>>(in, out);
}